// round 13
// baseline (speedup 1.0000x reference)
#include <cuda_runtime.h>
#include <cstdint>

#define BATCH   2
#define CF      64
#define NXD     468
#define NYD     468
#define GRID    (NXD * NYD)      // 219024
#define NP_PER  60000
#define HRD     48
#define WRD     512
#define RSP     (HRD * WRD)      // 24576
#define TCELL   64               // cells per gather tile (last tile has 16)
#define NTILES  ((GRID + TCELL - 1) / TCELL)   // 3423

// Winner-index maps: [0 .. B*G) spatial, [B*G .. 2*B*G) bev. -1 = empty.
__device__ __align__(16) int g_win[2 * BATCH * GRID];
// Channel-last transposed range_out: [B][RSP][64]
__device__ __align__(16) float g_rot[BATCH * RSP * CF];

#define SCAT_BLOCKS 625          // ceil(160000/256)
#define TRANS_BLOCKS (RSP / 32 * (CF / 32) * BATCH)   // 3072

// Fused prologue: blocks [0,625) scatter winners; blocks [625,3697) transpose
// range_out. Last-write-wins == highest point index (serial XLA scatter order).
// XLA's arcp rewrite makes v/0.16f == v*6.25f exactly (verified rel_err==0.0).
__global__ void __launch_bounds__(256) k_prologue(
        const int* __restrict__ vc, const float* __restrict__ lp,
        const float* __restrict__ ro, int n_pillar, int n_laser) {
    if (blockIdx.x < SCAT_BLOCKS) {
        int i = blockIdx.x * 256 + threadIdx.x;
        if (i < n_pillar) {
            int b   = vc[i * 4 + 0];
            int lin = vc[i * 4 + 1] + vc[i * 4 + 2] * NXD + vc[i * 4 + 3];
            if (b < 0 || b >= BATCH || lin < 0 || lin >= GRID) return;
            atomicMax(&g_win[b * GRID + lin], i);
        } else {
            int p = i - n_pillar;
            if (p >= n_laser) return;
            float x = lp[p * 5 + 1];
            float y = lp[p * 5 + 2];
            bool valid = (x > 0.0f) && (x < 69.12f) && (y > -39.68f) && (y < 39.68f)
                      && (x >= 0.0f) && (x < 468.0f) && (y >= 0.0f) && (y < 468.0f);
            if (!valid) return;
            int xi = (int)__fmul_rn(-y, 6.25f) + 248;   // XOFF
            int yi = (int)__fmul_rn(-x, 6.25f) + 432;   // YOFF
            xi = min(max(xi, 0), 495);
            yi = min(max(yi, 0), 431);
            if (xi >= NXD) return;                      // mode='drop'
            int b = p / NP_PER;
            atomicMax(&g_win[BATCH * GRID + b * GRID + yi * NXD + xi], p);
        }
    } else {
        // Transpose range_out (B,64,RSP) -> g_rot (B,RSP,64), 32x32 tiles.
        __shared__ float tile[32][33];
        int j  = blockIdx.x - SCAT_BLOCKS;
        int s0 = (j % (RSP / 32)) * 32;
        int c0 = ((j / (RSP / 32)) % (CF / 32)) * 32;
        int b  = j / (RSP / 32 * (CF / 32));
        int tx = threadIdx.x & 31, ty = threadIdx.x >> 5;   // (32, 8)
        #pragma unroll
        for (int k = 0; k < 4; k++) {
            int c = c0 + ty + k * 8;
            tile[ty + k * 8][tx] = ro[((size_t)(b * CF + c)) * RSP + s0 + tx];
        }
        __syncthreads();
        #pragma unroll
        for (int k = 0; k < 4; k++) {
            int s = s0 + ty + k * 8;
            g_rot[((size_t)(b * RSP + s)) * CF + c0 + tx] = tile[tx][ty + k * 8];
        }
    }
}

__device__ __forceinline__ unsigned int smem_u32(const void* p) {
    return (unsigned int)__cvta_generic_to_shared(p);
}

// Pipelined gather with ASYNC BULK STORES. Block = 64 cells x 128 ch in 4
// chunks of 32 ch (16 spatial + 16 bev rows), ping-pong 8 KB buffers with
// register prefetch of the next chunk (R7 skeleton, best measured config).
// The store phase is offloaded to the async copy engines: warp 0 lane l
// issues one cp.async.bulk (256B, smem row l -> out channel row) per chunk.
// SM-side work per chunk collapses to 2x LDG.128 + 8x STS per thread.
// Buffer reuse is guarded by per-lane bulk wait_group 1 (chunk c-2 done).
__global__ void __launch_bounds__(256) k_gather(
        const float* __restrict__ pf,
        const int*   __restrict__ lx,
        const int*   __restrict__ ly,
        const float* __restrict__ lp,
        float*       __restrict__ out) {
    __shared__ float buf[2][32][TCELL];    // 16 KB ping-pong chunk buffers
    __shared__ float s_zc[TCELL];
    __shared__ int   s_off[TCELL];
    __shared__ int   s_wiS[TCELL];

    int tile = blockIdx.x;
    int b    = blockIdx.y;
    int t    = threadIdx.x;
    int cell0  = tile * TCELL;
    int ncells = min(TCELL, GRID - cell0);

    if (t < TCELL) {
        int wiS = -1, wiB = -1;
        if (t < ncells) {
            wiS = g_win[b * GRID + cell0 + t];
            wiB = g_win[BATCH * GRID + b * GRID + cell0 + t];
        }
        s_wiS[t] = wiS;
        float zc = 0.0f; int off = -1;
        if (wiB >= 0) {
            float z = lp[wiB * 5 + 3];
            zc  = fminf(fmaxf(z, -2.0f), 4.0f);
            off = b * RSP + ly[wiB * 2 + 1] * WRD + lx[wiB * 2 + 1];
        }
        s_zc[t] = zc; s_off[t] = off;
    }
    __syncthreads();

    int cell = t & 63;
    int js   = t >> 6;                     // 0..3: quad within chunk half
    int wi   = s_wiS[cell];
    int off  = s_off[cell];
    float zc = s_zc[cell];

    float4 a, r;
    {   // Prefetch chunk 0.
        a = make_float4(0.f, 0.f, 0.f, 0.f);
        if (wi >= 0) a = *(const float4*)&pf[(size_t)wi * CF + js * 4];
        r = make_float4(0.f, 0.f, 0.f, 0.f);
        if (off >= 0) {
            r = *(const float4*)&g_rot[(size_t)off * CF + js * 4];
            r.x = __fmul_rn(zc, r.x); r.y = __fmul_rn(zc, r.y);
            r.z = __fmul_rn(zc, r.z); r.w = __fmul_rn(zc, r.w);
        }
    }

    size_t base  = (size_t)b * 128 * GRID + (size_t)cell0;
    int    bytes = ncells * 4;             // 256 (or 64 on the tail tile)

    #pragma unroll
    for (int c = 0; c < 4; c++) {
        float (*bc)[TCELL] = buf[c & 1];
        if (c >= 2 && t < 32) {
            // Ensure this lane's chunk c-2 bulk copy (from this buffer) is
            // done before overwriting. <=1 outstanding = newest (c-1) only.
            asm volatile("cp.async.bulk.wait_group 1;" ::: "memory");
        }
        __syncthreads();                   // buffer (c&1) free for all threads
        // Commit prefetched regs to smem (bank = cell mod 32, conflict-free).
        bc[js * 4 + 0][cell] = a.x;
        bc[js * 4 + 1][cell] = a.y;
        bc[js * 4 + 2][cell] = a.z;
        bc[js * 4 + 3][cell] = a.w;
        bc[16 + js * 4 + 0][cell] = r.x;
        bc[16 + js * 4 + 1][cell] = r.y;
        bc[16 + js * 4 + 2][cell] = r.z;
        bc[16 + js * 4 + 3][cell] = r.w;
        // Issue chunk c+1 gathers; latency hides under the async stores.
        if (c < 3) {
            int v = (c + 1) * 4 + js;
            a = make_float4(0.f, 0.f, 0.f, 0.f);
            if (wi >= 0) a = *(const float4*)&pf[(size_t)wi * CF + v * 4];
            r = make_float4(0.f, 0.f, 0.f, 0.f);
            if (off >= 0) {
                r = *(const float4*)&g_rot[(size_t)off * CF + v * 4];
                r.x = __fmul_rn(zc, r.x); r.y = __fmul_rn(zc, r.y);
                r.z = __fmul_rn(zc, r.z); r.w = __fmul_rn(zc, r.w);
            }
        }
        __syncthreads();                   // chunk c complete in bc
        // Warp 0: lane l ships smem row l (256B) to its output channel row.
        if (t < 32) {
            asm volatile("fence.proxy.async.shared::cta;" ::: "memory");
            int cl = t;                    // row 0..31
            int ch = (cl < 16) ? (c * 16 + cl) : (48 + c * 16 + cl);
            float* gp = out + base + (size_t)ch * GRID;
            unsigned int sp = smem_u32(&bc[cl][0]);
            asm volatile(
                "cp.async.bulk.global.shared::cta.bulk_group [%0], [%1], %2;"
                :: "l"(gp), "r"(sp), "r"(bytes) : "memory");
            asm volatile("cp.async.bulk.commit_group;" ::: "memory");
        }
    }
    // Final groups complete by kernel-boundary memory ordering.
}

extern "C" void kernel_launch(void* const* d_in, const int* in_sizes, int n_in,
                              void* d_out, int out_size) {
    const float* pf = (const float*)d_in[0];   // pillar_features (B*P_PER, 64)
    const int*   vc = (const int*)  d_in[1];   // voxel_coords    (B*P_PER, 4)
    const float* ro = (const float*)d_in[2];   // range_out       (B, 64, 48, 512)
    const int*   lx = (const int*)  d_in[3];   // laser_x         (B*NP, 2)
    const int*   ly = (const int*)  d_in[4];   // laser_y         (B*NP, 2)
    const float* lp = (const float*)d_in[5];   // laser_points    (B*NP, 5)
    float* out = (float*)d_out;

    int n_pillar = in_sizes[1] / 4;
    int n_laser  = in_sizes[5] / 5;

    void* winp = nullptr;
    cudaGetSymbolAddress(&winp, g_win);
    cudaMemsetAsync(winp, 0xFF, sizeof(int) * 2 * BATCH * GRID, 0);  // all -1

    k_prologue<<<SCAT_BLOCKS + TRANS_BLOCKS, 256>>>(vc, lp, ro, n_pillar, n_laser);

    dim3 gg(NTILES, BATCH);                    // (3423, 2)
    k_gather<<<gg, 256>>>(pf, lx, ly, lp, out);
}

// round 14
// speedup vs baseline: 1.2593x; 1.2593x over previous
#include <cuda_runtime.h>

#define BATCH   2
#define CF      64
#define NXD     468
#define NYD     468
#define GRID    (NXD * NYD)      // 219024
#define NP_PER  60000
#define HRD     48
#define WRD     512
#define RSP     (HRD * WRD)      // 24576
#define TCELL   64               // cells per gather tile (last tile has 16)
#define NTILES  ((GRID + TCELL - 1) / TCELL)   // 3423

// Winner-index maps: [0 .. B*G) spatial, [B*G .. 2*B*G) bev. -1 = empty.
__device__ __align__(16) int g_win[2 * BATCH * GRID];
// Channel-last transposed range_out: [B][RSP][64]
__device__ __align__(16) float g_rot[BATCH * RSP * CF];

#define SCAT_BLOCKS 625          // ceil(160000/256)
#define TRANS_BLOCKS (RSP / 32 * (CF / 32) * BATCH)   // 3072

// Fused prologue: blocks [0,625) scatter winners; blocks [625,3697) transpose
// range_out. Last-write-wins == highest point index (serial XLA scatter order).
// XLA's arcp rewrite makes v/0.16f == v*6.25f exactly (verified rel_err==0.0).
__global__ void __launch_bounds__(256) k_prologue(
        const int* __restrict__ vc, const float* __restrict__ lp,
        const float* __restrict__ ro, int n_pillar, int n_laser) {
    if (blockIdx.x < SCAT_BLOCKS) {
        int i = blockIdx.x * 256 + threadIdx.x;
        if (i < n_pillar) {
            int b   = vc[i * 4 + 0];
            int lin = vc[i * 4 + 1] + vc[i * 4 + 2] * NXD + vc[i * 4 + 3];
            if (b < 0 || b >= BATCH || lin < 0 || lin >= GRID) return;
            atomicMax(&g_win[b * GRID + lin], i);
        } else {
            int p = i - n_pillar;
            if (p >= n_laser) return;
            float x = lp[p * 5 + 1];
            float y = lp[p * 5 + 2];
            bool valid = (x > 0.0f) && (x < 69.12f) && (y > -39.68f) && (y < 39.68f)
                      && (x >= 0.0f) && (x < 468.0f) && (y >= 0.0f) && (y < 468.0f);
            if (!valid) return;
            int xi = (int)__fmul_rn(-y, 6.25f) + 248;   // XOFF
            int yi = (int)__fmul_rn(-x, 6.25f) + 432;   // YOFF
            xi = min(max(xi, 0), 495);
            yi = min(max(yi, 0), 431);
            if (xi >= NXD) return;                      // mode='drop'
            int b = p / NP_PER;
            atomicMax(&g_win[BATCH * GRID + b * GRID + yi * NXD + xi], p);
        }
    } else {
        // Transpose range_out (B,64,RSP) -> g_rot (B,RSP,64), 32x32 tiles.
        __shared__ float tile[32][33];
        int j  = blockIdx.x - SCAT_BLOCKS;
        int s0 = (j % (RSP / 32)) * 32;
        int c0 = ((j / (RSP / 32)) % (CF / 32)) * 32;
        int b  = j / (RSP / 32 * (CF / 32));
        int tx = threadIdx.x & 31, ty = threadIdx.x >> 5;   // (32, 8)
        #pragma unroll
        for (int k = 0; k < 4; k++) {
            int c = c0 + ty + k * 8;
            tile[ty + k * 8][tx] = ro[((size_t)(b * CF + c)) * RSP + s0 + tx];
        }
        __syncthreads();
        #pragma unroll
        for (int k = 0; k < 4; k++) {
            int s = s0 + ty + k * 8;
            g_rot[((size_t)(b * RSP + s)) * CF + c0 + tx] = tile[tx][ty + k * 8];
        }
    }
}

// R9 gather (best measured: 50.1 us) + __launch_bounds__(256, 8) to force
// <=32 regs -> 8 blocks/SM (was 38 regs -> 6 blocks, occ 69%). Block = 64
// cells x 128 ch in 2 chunks (spatial half, bev half). Full-row coalesced
// loads: cell = p*16 + (t>>4), v = t&15 -> 16 lanes read a winner row's
// 256B => 4 cache lines per warp-LDG. XOR swizzle col = cell ^ 2v:
// conflict-free scalar STS; store phase reads quad 4*(cv^(cl>>3)) of row
// cl with branchless half-swap when (cl>>2)&1, then STG.128.
__global__ void __launch_bounds__(256, 8) k_gather(
        const float* __restrict__ pf,
        const int*   __restrict__ lx,
        const int*   __restrict__ ly,
        const float* __restrict__ lp,
        float*       __restrict__ out) {
    __shared__ float s_val[64][64];        // 16 KB: [ch_local][swizzled cell]
    __shared__ float s_zc[TCELL];
    __shared__ int   s_off[TCELL];
    __shared__ int   s_wiS[TCELL];

    int tile = blockIdx.x;
    int b    = blockIdx.y;
    int t    = threadIdx.x;
    int cell0  = tile * TCELL;
    int ncells = min(TCELL, GRID - cell0);

    if (t < TCELL) {
        int wiS = -1, wiB = -1;
        if (t < ncells) {
            wiS = g_win[b * GRID + cell0 + t];
            wiB = g_win[BATCH * GRID + b * GRID + cell0 + t];
        }
        s_wiS[t] = wiS;
        float zc = 0.0f; int off = -1;
        if (wiB >= 0) {
            float z = lp[wiB * 5 + 3];
            zc  = fminf(fmaxf(z, -2.0f), 4.0f);
            off = b * RSP + ly[wiB * 2 + 1] * WRD + lx[wiB * 2 + 1];
        }
        s_zc[t] = zc; s_off[t] = off;
    }
    __syncthreads();

    int crel = t >> 4;                     // 0..15: cell within pass group
    int v    = t & 15;                     // quad 0..15 = full row coverage
    size_t base = (size_t)b * 128 * GRID + (size_t)cell0;

    float4 d[4];
    // ---- Chunk A (spatial): load 4 passes, full-row coalesced ----
    #pragma unroll
    for (int p = 0; p < 4; p++) {
        int cell = p * 16 + crel;
        int wi = s_wiS[cell];
        d[p] = make_float4(0.f, 0.f, 0.f, 0.f);
        if (wi >= 0) d[p] = *(const float4*)&pf[(size_t)wi * CF + v * 4];
    }
    // STS chunk A (swizzled, conflict-free).
    #pragma unroll
    for (int p = 0; p < 4; p++) {
        int cell = p * 16 + crel;
        int col  = (cell ^ (2 * v)) & 63;
        float va[4] = {d[p].x, d[p].y, d[p].z, d[p].w};
        #pragma unroll
        for (int k = 0; k < 4; k++) s_val[v * 4 + k][col] = va[k];
    }
    // ---- Prefetch chunk B (bev) into regs; hides under A's store phase ----
    #pragma unroll
    for (int p = 0; p < 4; p++) {
        int cell = p * 16 + crel;
        int off  = s_off[cell];
        float4 r = make_float4(0.f, 0.f, 0.f, 0.f);
        if (off >= 0) {
            float zc = s_zc[cell];
            r = *(const float4*)&g_rot[(size_t)off * CF + v * 4];
            r.x = __fmul_rn(zc, r.x); r.y = __fmul_rn(zc, r.y);
            r.z = __fmul_rn(zc, r.z); r.w = __fmul_rn(zc, r.w);
        }
        d[p] = r;
    }
    __syncthreads();
    // ---- Store chunk A: LDS.128 + STG.128, coalesced 256B per 16 lanes ----
    #pragma unroll
    for (int it = 0; it < 4; it++) {
        int s  = t + it * 256;
        int cl = s >> 4;                   // channel 0..63
        int cv = s & 15;                   // cell quad
        if (cv * 4 < ncells) {
            int G = cv ^ (cl >> 3);
            float4 o = *(const float4*)&s_val[cl][G * 4];
            if ((cl >> 2) & 1) o = make_float4(o.z, o.w, o.x, o.y);
            __stcs((float4*)&out[base + (size_t)cl * GRID + cv * 4], o);
        }
    }
    __syncthreads();
    // ---- STS chunk B ----
    #pragma unroll
    for (int p = 0; p < 4; p++) {
        int cell = p * 16 + crel;
        int col  = (cell ^ (2 * v)) & 63;
        float vr[4] = {d[p].x, d[p].y, d[p].z, d[p].w};
        #pragma unroll
        for (int k = 0; k < 4; k++) s_val[v * 4 + k][col] = vr[k];
    }
    __syncthreads();
    // ---- Store chunk B (channels 64..127) ----
    #pragma unroll
    for (int it = 0; it < 4; it++) {
        int s  = t + it * 256;
        int cl = s >> 4;
        int cv = s & 15;
        if (cv * 4 < ncells) {
            int G = cv ^ (cl >> 3);
            float4 o = *(const float4*)&s_val[cl][G * 4];
            if ((cl >> 2) & 1) o = make_float4(o.z, o.w, o.x, o.y);
            __stcs((float4*)&out[base + (size_t)(CF + cl) * GRID + cv * 4], o);
        }
    }
}

extern "C" void kernel_launch(void* const* d_in, const int* in_sizes, int n_in,
                              void* d_out, int out_size) {
    const float* pf = (const float*)d_in[0];   // pillar_features (B*P_PER, 64)
    const int*   vc = (const int*)  d_in[1];   // voxel_coords    (B*P_PER, 4)
    const float* ro = (const float*)d_in[2];   // range_out       (B, 64, 48, 512)
    const int*   lx = (const int*)  d_in[3];   // laser_x         (B*NP, 2)
    const int*   ly = (const int*)  d_in[4];   // laser_y         (B*NP, 2)
    const float* lp = (const float*)d_in[5];   // laser_points    (B*NP, 5)
    float* out = (float*)d_out;

    int n_pillar = in_sizes[1] / 4;
    int n_laser  = in_sizes[5] / 5;

    void* winp = nullptr;
    cudaGetSymbolAddress(&winp, g_win);
    cudaMemsetAsync(winp, 0xFF, sizeof(int) * 2 * BATCH * GRID, 0);  // all -1

    k_prologue<<<SCAT_BLOCKS + TRANS_BLOCKS, 256>>>(vc, lp, ro, n_pillar, n_laser);

    dim3 gg(NTILES, BATCH);                    // (3423, 2)
    k_gather<<<gg, 256>>>(pf, lx, ly, lp, out);
}

// round 15
// speedup vs baseline: 1.2945x; 1.0280x over previous
#include <cuda_runtime.h>

#define BATCH   2
#define CF      64
#define NXD     468
#define NYD     468
#define GRID    (NXD * NYD)      // 219024
#define NP_PER  60000
#define HRD     48
#define WRD     512
#define RSP     (HRD * WRD)      // 24576
#define TCELL   64               // cells per gather tile (last tile has 16)
#define NTILES  ((GRID + TCELL - 1) / TCELL)   // 3423

// Winner-index maps: [0 .. B*G) spatial, [B*G .. 2*B*G) bev. -1 = empty.
__device__ __align__(16) int g_win[2 * BATCH * GRID];
// Channel-last transposed range_out: [B][RSP][64]
__device__ __align__(16) float g_rot[BATCH * RSP * CF];

#define SCAT_BLOCKS 625          // ceil(160000/256)
#define TRANS_BLOCKS (RSP / 128 * (CF / 32) * BATCH)   // 192*2*2 = 768

// Fused prologue: blocks [0,625) scatter winners; blocks [625,1393) transpose
// range_out. Last-write-wins == highest point index (serial XLA scatter order).
// XLA's arcp rewrite makes v/0.16f == v*6.25f exactly (verified rel_err==0.0).
__global__ void __launch_bounds__(256) k_prologue(
        const int* __restrict__ vc, const float* __restrict__ lp,
        const float* __restrict__ ro, int n_pillar, int n_laser) {
    if (blockIdx.x < SCAT_BLOCKS) {
        int i = blockIdx.x * 256 + threadIdx.x;
        if (i < n_pillar) {
            int b   = vc[i * 4 + 0];
            int lin = vc[i * 4 + 1] + vc[i * 4 + 2] * NXD + vc[i * 4 + 3];
            if (b < 0 || b >= BATCH || lin < 0 || lin >= GRID) return;
            atomicMax(&g_win[b * GRID + lin], i);
        } else {
            int p = i - n_pillar;
            if (p >= n_laser) return;
            float x = lp[p * 5 + 1];
            float y = lp[p * 5 + 2];
            bool valid = (x > 0.0f) && (x < 69.12f) && (y > -39.68f) && (y < 39.68f)
                      && (x >= 0.0f) && (x < 468.0f) && (y >= 0.0f) && (y < 468.0f);
            if (!valid) return;
            int xi = (int)__fmul_rn(-y, 6.25f) + 248;   // XOFF
            int yi = (int)__fmul_rn(-x, 6.25f) + 432;   // YOFF
            xi = min(max(xi, 0), 495);
            yi = min(max(yi, 0), 431);
            if (xi >= NXD) return;                      // mode='drop'
            int b = p / NP_PER;
            atomicMax(&g_win[BATCH * GRID + b * GRID + yi * NXD + xi], p);
        }
    } else {
        // Vectorized transpose: ro (B,64,RSP) -> g_rot (B,RSP,64).
        // Tile = 32 channels x 128 pixels. LDG.128 in, STG.128 out.
        // smem [32][129] with column map phi(p) = (p&3)*32 + (p>>2):
        //  - load STS (lanes q, fixed c): bank = (c + q) % 32, conflict-free
        //  - store LDS (lanes v,pr): bank = (4v + j + (p>>2)) % 32, all 32
        __shared__ float tl[32][129];
        int j  = blockIdx.x - SCAT_BLOCKS;     // 0..767
        int sI = j % (RSP / 128);              // 0..191
        int cI = (j / (RSP / 128)) & 1;        // channel chunk
        int b  = j / (RSP / 128 * 2);
        int s0 = sI * 128;
        int c0 = cI * 32;
        int t  = threadIdx.x;
        int q  = t & 31;
        #pragma unroll
        for (int k = 0; k < 4; k++) {
            int c = k * 8 + (t >> 5);
            float4 d = *(const float4*)&ro[(size_t)(b * CF + c0 + c) * RSP
                                           + s0 + q * 4];
            tl[c][0 * 32 + q] = d.x;           // pixel q*4+0 -> phi = 0*32+q
            tl[c][1 * 32 + q] = d.y;
            tl[c][2 * 32 + q] = d.z;
            tl[c][3 * 32 + q] = d.w;
        }
        __syncthreads();
        int v = t & 7;
        #pragma unroll
        for (int it = 0; it < 4; it++) {
            int p   = 4 * (t >> 3) + it;       // pixel 0..127, stride-4 lanes
            int phi = it * 32 + (t >> 3);      // (p&3)*32 + (p>>2)
            float4 o;
            o.x = tl[4 * v + 0][phi];
            o.y = tl[4 * v + 1][phi];
            o.z = tl[4 * v + 2][phi];
            o.w = tl[4 * v + 3][phi];
            *(float4*)&g_rot[(size_t)(b * RSP + s0 + p) * CF + c0 + v * 4] = o;
        }
    }
}

// R14 gather unchanged (best measured: 46.8 us, occ 90.6%). Block = 64
// cells x 128 ch in 2 chunks (spatial half, bev half). Full-row coalesced
// loads: cell = p*16 + (t>>4), v = t&15 -> 16 lanes read a winner row's
// 256B => 4 cache lines per warp-LDG. XOR swizzle col = cell ^ 2v:
// conflict-free scalar STS; store phase reads quad 4*(cv^(cl>>3)) of row
// cl with branchless half-swap when (cl>>2)&1, then STG.128.
__global__ void __launch_bounds__(256, 8) k_gather(
        const float* __restrict__ pf,
        const int*   __restrict__ lx,
        const int*   __restrict__ ly,
        const float* __restrict__ lp,
        float*       __restrict__ out) {
    __shared__ float s_val[64][64];        // 16 KB: [ch_local][swizzled cell]
    __shared__ float s_zc[TCELL];
    __shared__ int   s_off[TCELL];
    __shared__ int   s_wiS[TCELL];

    int tile = blockIdx.x;
    int b    = blockIdx.y;
    int t    = threadIdx.x;
    int cell0  = tile * TCELL;
    int ncells = min(TCELL, GRID - cell0);

    if (t < TCELL) {
        int wiS = -1, wiB = -1;
        if (t < ncells) {
            wiS = g_win[b * GRID + cell0 + t];
            wiB = g_win[BATCH * GRID + b * GRID + cell0 + t];
        }
        s_wiS[t] = wiS;
        float zc = 0.0f; int off = -1;
        if (wiB >= 0) {
            float z = lp[wiB * 5 + 3];
            zc  = fminf(fmaxf(z, -2.0f), 4.0f);
            off = b * RSP + ly[wiB * 2 + 1] * WRD + lx[wiB * 2 + 1];
        }
        s_zc[t] = zc; s_off[t] = off;
    }
    __syncthreads();

    int crel = t >> 4;                     // 0..15: cell within pass group
    int v    = t & 15;                     // quad 0..15 = full row coverage
    size_t base = (size_t)b * 128 * GRID + (size_t)cell0;

    float4 d[4];
    // ---- Chunk A (spatial): load 4 passes, full-row coalesced ----
    #pragma unroll
    for (int p = 0; p < 4; p++) {
        int cell = p * 16 + crel;
        int wi = s_wiS[cell];
        d[p] = make_float4(0.f, 0.f, 0.f, 0.f);
        if (wi >= 0) d[p] = *(const float4*)&pf[(size_t)wi * CF + v * 4];
    }
    // STS chunk A (swizzled, conflict-free).
    #pragma unroll
    for (int p = 0; p < 4; p++) {
        int cell = p * 16 + crel;
        int col  = (cell ^ (2 * v)) & 63;
        float va[4] = {d[p].x, d[p].y, d[p].z, d[p].w};
        #pragma unroll
        for (int k = 0; k < 4; k++) s_val[v * 4 + k][col] = va[k];
    }
    // ---- Prefetch chunk B (bev) into regs; hides under A's store phase ----
    #pragma unroll
    for (int p = 0; p < 4; p++) {
        int cell = p * 16 + crel;
        int off  = s_off[cell];
        float4 r = make_float4(0.f, 0.f, 0.f, 0.f);
        if (off >= 0) {
            float zc = s_zc[cell];
            r = *(const float4*)&g_rot[(size_t)off * CF + v * 4];
            r.x = __fmul_rn(zc, r.x); r.y = __fmul_rn(zc, r.y);
            r.z = __fmul_rn(zc, r.z); r.w = __fmul_rn(zc, r.w);
        }
        d[p] = r;
    }
    __syncthreads();
    // ---- Store chunk A: LDS.128 + STG.128, coalesced 256B per 16 lanes ----
    #pragma unroll
    for (int it = 0; it < 4; it++) {
        int s  = t + it * 256;
        int cl = s >> 4;                   // channel 0..63
        int cv = s & 15;                   // cell quad
        if (cv * 4 < ncells) {
            int G = cv ^ (cl >> 3);
            float4 o = *(const float4*)&s_val[cl][G * 4];
            if ((cl >> 2) & 1) o = make_float4(o.z, o.w, o.x, o.y);
            __stcs((float4*)&out[base + (size_t)cl * GRID + cv * 4], o);
        }
    }
    __syncthreads();
    // ---- STS chunk B ----
    #pragma unroll
    for (int p = 0; p < 4; p++) {
        int cell = p * 16 + crel;
        int col  = (cell ^ (2 * v)) & 63;
        float vr[4] = {d[p].x, d[p].y, d[p].z, d[p].w};
        #pragma unroll
        for (int k = 0; k < 4; k++) s_val[v * 4 + k][col] = vr[k];
    }
    __syncthreads();
    // ---- Store chunk B (channels 64..127) ----
    #pragma unroll
    for (int it = 0; it < 4; it++) {
        int s  = t + it * 256;
        int cl = s >> 4;
        int cv = s & 15;
        if (cv * 4 < ncells) {
            int G = cv ^ (cl >> 3);
            float4 o = *(const float4*)&s_val[cl][G * 4];
            if ((cl >> 2) & 1) o = make_float4(o.z, o.w, o.x, o.y);
            __stcs((float4*)&out[base + (size_t)(CF + cl) * GRID + cv * 4], o);
        }
    }
}

extern "C" void kernel_launch(void* const* d_in, const int* in_sizes, int n_in,
                              void* d_out, int out_size) {
    const float* pf = (const float*)d_in[0];   // pillar_features (B*P_PER, 64)
    const int*   vc = (const int*)  d_in[1];   // voxel_coords    (B*P_PER, 4)
    const float* ro = (const float*)d_in[2];   // range_out       (B, 64, 48, 512)
    const int*   lx = (const int*)  d_in[3];   // laser_x         (B*NP, 2)
    const int*   ly = (const int*)  d_in[4];   // laser_y         (B*NP, 2)
    const float* lp = (const float*)d_in[5];   // laser_points    (B*NP, 5)
    float* out = (float*)d_out;

    int n_pillar = in_sizes[1] / 4;
    int n_laser  = in_sizes[5] / 5;

    void* winp = nullptr;
    cudaGetSymbolAddress(&winp, g_win);
    cudaMemsetAsync(winp, 0xFF, sizeof(int) * 2 * BATCH * GRID, 0);  // all -1

    k_prologue<<<SCAT_BLOCKS + TRANS_BLOCKS, 256>>>(vc, lp, ro, n_pillar, n_laser);

    dim3 gg(NTILES, BATCH);                    // (3423, 2)
    k_gather<<<gg, 256>>>(pf, lx, ly, lp, out);
}